// round 11
// baseline (speedup 1.0000x reference)
#include <cuda_runtime.h>
#include <cstdint>

#define BB 128
#define TT 2048
#define NI 128
#define NH 128
#define TILE_T 64
#define N_TILES (TT / TILE_T)   // 32
#define RING_SLOTS 128          // 2 tiles

typedef unsigned long long ull;

// ---------------- packed f32x2 ----------------
#define FMA_F32X2(d, a, b, c) \
    asm("fma.rn.f32x2 %0, %1, %2, %3;" : "=l"(d) : "l"(a), "l"(b), "l"(c))
#define ADD_F32X2_(d, a, b) \
    asm("add.rn.f32x2 %0, %1, %2;" : "=l"(d) : "l"(a), "l"(b))
#define PACK2_F32X2(out, lo, hi) \
    asm("mov.b64 %0, {%1, %2};" : "=l"(out) : "f"(lo), "f"(hi))

#define BAR_PROD() asm volatile("bar.sync 1, 128;" ::: "memory")
#define BAR_CONS() asm volatile("bar.sync 2, 256;" ::: "memory")

__device__ __forceinline__ uint32_t tf32hi(float x) {
    uint32_t u;
    asm("cvt.rna.tf32.f32 %0, %1;" : "=r"(u) : "f"(x));
    return u;
}
__device__ __forceinline__ int ld_acquire_shared(const int* p) {
    int v;
    asm volatile("ld.acquire.cta.shared.b32 %0, [%1];"
                 : "=r"(v) : "r"((unsigned)__cvta_generic_to_shared(p)) : "memory");
    return v;
}
__device__ __forceinline__ void st_release_shared(int* p, int v) {
    asm volatile("st.release.cta.shared.b32 [%0], %1;"
                 :: "r"((unsigned)__cvta_generic_to_shared(p)), "r"(v) : "memory");
}

// tf32 mma m16n8k8 (baseline PTX, legal on compute_103)
#define MMA_TF32(c0,c1,c2,c3, a0,a1,a2,a3, b0,b1)                            \
    asm volatile("mma.sync.aligned.m16n8k8.row.col.f32.tf32.tf32.f32 "       \
        "{%0,%1,%2,%3}, {%4,%5,%6,%7}, {%8,%9}, {%0,%1,%2,%3};"              \
        : "+f"(c0), "+f"(c1), "+f"(c2), "+f"(c3)                             \
        : "r"(a0), "r"(a1), "r"(a2), "r"(a3), "r"(b0), "r"(b1))

// ---------------- smem layout (float indices) ----------------
#define WHI_F    0                    // W_in hi fragments   (16384 f)
#define WLO_F    16384                // W_in lo fragments   (16384 f)
#define AF_F     32768                // A tile fragments     (8192 f)
#define RING_F   40960                // ring [128][128]     (16384 f)
#define HA_F     57344                // z buffer A (128 f)
#define HB_F     57472                // z buffer B (128 f)
#define ROWS_F   57600                // 0.25*rowsum(W_hh) (128 f)
#define FLAGS_F  57728
#define SMEM_F   57736                // 230944 B

// 16 FFMA2: 8 ulonglong2 (32 z floats) against W[0..15]
#define FMA_CHUNK(C0,C1,C2,C3,C4,C5,C6,C7, W)                               \
    FMA_F32X2(a0, (W)[ 0], C0.x, a0); FMA_F32X2(a1, (W)[ 1], C0.y, a1);     \
    FMA_F32X2(a2, (W)[ 2], C1.x, a2); FMA_F32X2(a3, (W)[ 3], C1.y, a3);     \
    FMA_F32X2(a0, (W)[ 4], C2.x, a0); FMA_F32X2(a1, (W)[ 5], C2.y, a1);     \
    FMA_F32X2(a2, (W)[ 6], C3.x, a2); FMA_F32X2(a3, (W)[ 7], C3.y, a3);     \
    FMA_F32X2(a0, (W)[ 8], C4.x, a0); FMA_F32X2(a1, (W)[ 9], C4.y, a1);     \
    FMA_F32X2(a2, (W)[10], C5.x, a2); FMA_F32X2(a3, (W)[11], C5.y, a3);     \
    FMA_F32X2(a0, (W)[12], C6.x, a0); FMA_F32X2(a1, (W)[13], C6.y, a1);     \
    FMA_F32X2(a2, (W)[14], C7.x, a2); FMA_F32X2(a3, (W)[15], C7.y, a3);

// One scan step (z-exchange form). Per thread: 16 LDS.128 + 32 FFMA2,
// halves combined by shfl_xor(16). ig (from ring) already contains
// 0.5*(igate + b_in + b_hh) + 0.25*rowsum_j.
#define SCAN_STEP(ZSRC, ZDST)                                                \
{                                                                            \
    float ig_h = *igp; igp += NH;                                            \
    const ulonglong2* h2 = (const ulonglong2*)(ZSRC) + (half << 4);          \
    ull a0 = 0ULL, a1 = 0ULL, a2 = 0ULL, a3 = 0ULL;                          \
    ulonglong2 p0 = h2[0], p1 = h2[1], p2 = h2[2], p3 = h2[3];               \
    ulonglong2 p4 = h2[4], p5 = h2[5], p6 = h2[6], p7 = h2[7];               \
    ulonglong2 q0 = h2[ 8], q1 = h2[ 9], q2 = h2[10], q3 = h2[11];           \
    ulonglong2 q4 = h2[12], q5 = h2[13], q6 = h2[14], q7 = h2[15];           \
    FMA_CHUNK(p0,p1,p2,p3,p4,p5,p6,p7, w2 + 0)                               \
    FMA_CHUNK(q0,q1,q2,q3,q4,q5,q6,q7, w2 + 16)                              \
    ull s01, s23, s;                                                         \
    ADD_F32X2_(s01, a0, a1);                                                 \
    ADD_F32X2_(s23, a2, a3);                                                 \
    ADD_F32X2_(s, s01, s23);                                                 \
    float2 sp = *reinterpret_cast<float2*>(&s);                              \
    float pmine = sp.x + sp.y;                                               \
    float pother = __shfl_xor_sync(0xFFFFFFFFu, pmine, 16);                  \
    float pre = (pmine + pother) + ig_h;                                     \
    float z;                                                                 \
    asm("tanh.approx.f32 %0, %1;" : "=f"(z) : "f"(pre));                     \
    if (lane < 16) (ZDST)[j] = z;                                            \
    float h = fmaf(0.5f, z, 0.5f);                                           \
    if (lane < 16) __stcs(rowp, h);                                          \
    rowp += NH;                                                              \
    BAR_CONS();                                                              \
}

// ======================================================================
// Fused kernel: 128 CTAs x 384 threads.
//   warps 0-3  (tid 0-127):   PRODUCER — tf32 mma.sync -> smem ring
//   warps 4-11 (tid 128-383): CONSUMER — scan, 16 j x 2 i-halves per warp
// ======================================================================
extern __shared__ float g_smem[];

__global__ void __launch_bounds__(384, 1) fused_rnn_kernel(
    const float* __restrict__ inp,      // [B,T,NI]
    const float* __restrict__ hidden0,  // [B,NH]
    const float* __restrict__ W_in,     // [NH,NI]
    const float* __restrict__ b_in,     // [NH]
    const float* __restrict__ W_hh,     // [NH,NH]
    const float* __restrict__ b_hh,     // [NH]
    float* __restrict__ out)            // [B,T,NH]
{
    float* Whi  = g_smem + WHI_F;
    float* Wlo  = g_smem + WLO_F;
    float* AF   = g_smem + AF_F;
    float* ring = g_smem + RING_F;
    float* rows = g_smem + ROWS_F;
    int*  flags = (int*)(g_smem + FLAGS_F);

    const int tid = threadIdx.x;
    const int wid = tid >> 5;
    const int lane = tid & 31;
    const int b = blockIdx.x;

    if (tid == 0) { flags[0] = 0; flags[1] = 0; }

    // ---- 0.25 * rowsum of W_hh (for the z-form constant) ----
    if (tid < 128) {
        float s = 0.f;
        const float4* wr = (const float4*)(W_hh + (long)tid * NH);
        #pragma unroll
        for (int i = 0; i < 32; i++) {
            float4 v = wr[i];
            s += (v.x + v.y) + (v.z + v.w);
        }
        rows[tid] = 0.25f * s;
    }

    // ---- W_in hi/lo fragment prep (all 384 threads, once) ----
    for (int idx = tid; idx < 128 * 32; idx += 384) {
        int jj = idx >> 5;
        int g4 = idx & 31;
        int k  = g4 * 4;
        float4 v = *(const float4*)(W_in + (long)jj * NI + k);
        float vf[4] = {v.x, v.y, v.z, v.w};
        int nt = jj >> 3, gg = jj & 7, ks = k >> 3;
        int halfk = (k & 7) >= 4 ? 1 : 0;
        #pragma unroll
        for (int e = 0; e < 4; e++) {
            uint32_t hu = tf32hi(vf[e]);
            float hf = __uint_as_float(hu);
            uint32_t lu = tf32hi(vf[e] - hf);
            int fa = ((nt * 16 + ks) * 32 + (gg * 4 + e)) * 2 + halfk;
            Whi[fa] = __uint_as_float(hu);
            Wlo[fa] = __uint_as_float(lu);
        }
    }
    __syncthreads();   // prep + rowsum done; roles split below

    if (tid < 128) {
        // ============================ PRODUCER ============================
        const float* binp = inp + (long)b * TT * NI;
        const int g  = lane >> 2;   // 0..7
        const int tg = lane & 3;    // 0..3

        // bias pairs: 0.5*(b_in+b_hh)[j] + 0.25*rowsum[j]
        float2 biasf[16];
        #pragma unroll
        for (int nt = 0; nt < 16; nt++) {
            int j0 = nt * 8 + tg * 2;
            biasf[nt].x = 0.5f * (b_in[j0]     + b_hh[j0])     + rows[j0];
            biasf[nt].y = 0.5f * (b_in[j0 + 1] + b_hh[j0 + 1]) + rows[j0 + 1];
        }

        for (int kt = 0; kt < N_TILES; kt++) {
            const long t0 = (long)kt * TILE_T;

            if (kt >= 2) {
                while (ld_acquire_shared(&flags[1]) < kt - 1) __nanosleep(64);
            }

            // scatter input tile into A-fragment layout
            #pragma unroll
            for (int it = 0; it < 16; it++) {
                int f = tid + it * 128;          // 0..2047 float4 units
                int r = f >> 5;                  // 0..63
                int g4 = f & 31;
                int k = g4 * 4;
                float4 v = __ldcs((const float4*)(binp + (t0 + r) * NI + k));
                float vf[4] = {v.x, v.y, v.z, v.w};
                int w = r >> 4, ks = k >> 3;
                int reg = (((r & 15) >= 8) ? 1 : 0) + (((k & 7) >= 4) ? 2 : 0);
                int baseaddr = ((w * 16 + ks) * 32 + (r & 7) * 4) * 4 + reg;
                #pragma unroll
                for (int e = 0; e < 4; e++)
                    AF[baseaddr + e * 4] = vf[e];
            }
            BAR_PROD();

            // load this warp's A fragments, split hi/lo
            uint32_t ah[16][4], al[16][4];
            #pragma unroll
            for (int ks = 0; ks < 16; ks++) {
                float4 v = *(const float4*)(AF + ((wid * 16 + ks) * 32 + lane) * 4);
                float vf[4] = {v.x, v.y, v.z, v.w};
                #pragma unroll
                for (int e = 0; e < 4; e++) {
                    ah[ks][e] = tf32hi(vf[e]);
                    al[ks][e] = tf32hi(vf[e] - __uint_as_float(ah[ks][e]));
                }
            }

            // 16 n-tiles x 16 k-steps x 3 mma
            #pragma unroll 1
            for (int nt = 0; nt < 16; nt++) {
                float c0 = 0.f, c1 = 0.f, c2 = 0.f, c3 = 0.f;
                const float2* bhp = (const float2*)(Whi + (nt * 16 * 32) * 2) + lane;
                const float2* blp = (const float2*)(Wlo + (nt * 16 * 32) * 2) + lane;
                #pragma unroll
                for (int ks = 0; ks < 16; ks++) {
                    float2 bh = bhp[ks * 32];
                    float2 bl = blp[ks * 32];
                    uint32_t bh0 = __float_as_uint(bh.x), bh1 = __float_as_uint(bh.y);
                    uint32_t bl0 = __float_as_uint(bl.x), bl1 = __float_as_uint(bl.y);
                    MMA_TF32(c0,c1,c2,c3, ah[ks][0],ah[ks][1],ah[ks][2],ah[ks][3], bh0,bh1);
                    MMA_TF32(c0,c1,c2,c3, al[ks][0],al[ks][1],al[ks][2],al[ks][3], bh0,bh1);
                    MMA_TF32(c0,c1,c2,c3, ah[ks][0],ah[ks][1],ah[ks][2],ah[ks][3], bl0,bl1);
                }
                int j0 = nt * 8 + tg * 2;
                int slot0 = (int)((t0 + wid * 16 + g) & (RING_SLOTS - 1));
                int slot1 = (int)((t0 + wid * 16 + g + 8) & (RING_SLOTS - 1));
                *(float2*)(ring + slot0 * NH + j0) =
                    make_float2(fmaf(0.5f, c0, biasf[nt].x), fmaf(0.5f, c1, biasf[nt].y));
                *(float2*)(ring + slot1 * NH + j0) =
                    make_float2(fmaf(0.5f, c2, biasf[nt].x), fmaf(0.5f, c3, biasf[nt].y));
            }
            BAR_PROD();
            if (tid == 0) st_release_shared(&flags[0], kt + 1);
        }
    } else {
        // ============================ CONSUMER ============================
        const int cwid = wid - 4;               // 0..7
        const int j = (cwid << 4) | (lane & 15);  // 0..127
        const int half = lane >> 4;             // 0 or 1
        float* zA = g_smem + HA_F;
        float* zB = g_smem + HB_F;

        // 0.25*W_hh[j][half*64 .. half*64+63] as 32 packed pairs (64 regs)
        ull w2[32];
        {
            const float4* wrow = (const float4*)(W_hh + (long)j * NH + half * 64);
            #pragma unroll
            for (int i = 0; i < 16; i++) {
                float4 v = wrow[i];
                PACK2_F32X2(w2[2 * i],     0.25f * v.x, 0.25f * v.y);
                PACK2_F32X2(w2[2 * i + 1], 0.25f * v.z, 0.25f * v.w);
            }
        }

        if (lane < 16) zA[j] = fmaf(2.0f, hidden0[(long)b * NH + j], -1.0f);

        float* rowp = out + (long)b * TT * NH + j;

        BAR_CONS();   // zA visible to all consumer threads

        #pragma unroll 1
        for (int tb = 0; tb < N_TILES; tb++) {
            while (ld_acquire_shared(&flags[0]) < tb + 1) __nanosleep(64);
            const float* igp = ring + (((long)tb * TILE_T & (RING_SLOTS - 1)) * NH) + j;

            #pragma unroll 1
            for (int tt = 0; tt < TILE_T; tt += 2) {
                SCAN_STEP(zA, zB)
                SCAN_STEP(zB, zA)
            }
            if (tid == 128) st_release_shared(&flags[1], tb + 1);
        }
    }
}

// ======================================================================
extern "C" void kernel_launch(void* const* d_in, const int* in_sizes, int n_in,
                              void* d_out, int out_size)
{
    const float* inp     = (const float*)d_in[0];  // [B,T,NI]
    const float* hidden0 = (const float*)d_in[1];  // [B,NH]
    const float* W_in    = (const float*)d_in[2];  // [NH,NI]
    const float* b_in    = (const float*)d_in[3];  // [NH]
    const float* W_hh    = (const float*)d_in[4];  // [NH,NH]
    const float* b_hh    = (const float*)d_in[5];  // [NH]
    float* out = (float*)d_out;                    // [B,T,NH]

    const int smem_bytes = SMEM_F * 4;   // 230944 B
    cudaFuncSetAttribute(fused_rnn_kernel,
                         cudaFuncAttributeMaxDynamicSharedMemorySize, smem_bytes);

    fused_rnn_kernel<<<BB, 384, smem_bytes>>>(inp, hidden0, W_in, b_in,
                                              W_hh, b_hh, out);
}

// round 12
// speedup vs baseline: 1.3282x; 1.3282x over previous
#include <cuda_runtime.h>
#include <cstdint>

#define BB 128
#define TT 2048
#define NI 128
#define NH 128
#define TILE_T 64
#define N_TILES (TT / TILE_T)   // 32
#define RING_SLOTS 128          // 2 tiles

typedef unsigned long long ull;

// ---------------- packed f32x2 ----------------
#define FMA_F32X2(d, a, b, c) \
    asm("fma.rn.f32x2 %0, %1, %2, %3;" : "=l"(d) : "l"(a), "l"(b), "l"(c))
#define ADD_F32X2_(d, a, b) \
    asm("add.rn.f32x2 %0, %1, %2;" : "=l"(d) : "l"(a), "l"(b))
#define PACK2_F32X2(out, lo, hi) \
    asm("mov.b64 %0, {%1, %2};" : "=l"(out) : "f"(lo), "f"(hi))

#define BAR_PROD() asm volatile("bar.sync 1, 128;" ::: "memory")
#define BAR_CONS() asm volatile("bar.sync 2, 128;" ::: "memory")

__device__ __forceinline__ uint32_t tf32hi(float x) {
    uint32_t u;
    asm("cvt.rna.tf32.f32 %0, %1;" : "=r"(u) : "f"(x));
    return u;
}
__device__ __forceinline__ int ld_acquire_shared(const int* p) {
    int v;
    asm volatile("ld.acquire.cta.shared.b32 %0, [%1];"
                 : "=r"(v) : "r"((unsigned)__cvta_generic_to_shared(p)) : "memory");
    return v;
}
__device__ __forceinline__ void st_release_shared(int* p, int v) {
    asm volatile("st.release.cta.shared.b32 [%0], %1;"
                 :: "r"((unsigned)__cvta_generic_to_shared(p)), "r"(v) : "memory");
}

// tf32 mma m16n8k8 (baseline PTX, legal on compute_103)
#define MMA_TF32(c0,c1,c2,c3, a0,a1,a2,a3, b0,b1)                            \
    asm volatile("mma.sync.aligned.m16n8k8.row.col.f32.tf32.tf32.f32 "       \
        "{%0,%1,%2,%3}, {%4,%5,%6,%7}, {%8,%9}, {%0,%1,%2,%3};"              \
        : "+f"(c0), "+f"(c1), "+f"(c2), "+f"(c3)                             \
        : "r"(a0), "r"(a1), "r"(a2), "r"(a3), "r"(b0), "r"(b1))

// ---------------- smem layout (float indices) ----------------
#define WHI_F    0                    // W_in hi fragments   (16384 f)
#define WLO_F    16384                // W_in lo fragments   (16384 f)
#define AF_F     32768                // A tile fragments     (8192 f)
#define RING_F   40960                // ring [128][128]     (16384 f)
#define HA_F     57344
#define HB_F     57472
#define FLAGS_F  57600
#define SMEM_F   57608                // 230432 B

// 16 FFMA2 of one 32-float chunk against W[0..15]
#define FMA_CHUNK(C0,C1,C2,C3,C4,C5,C6,C7, W)                               \
    FMA_F32X2(a0, (W)[ 0], C0.x, a0); FMA_F32X2(a1, (W)[ 1], C0.y, a1);     \
    FMA_F32X2(a2, (W)[ 2], C1.x, a2); FMA_F32X2(a3, (W)[ 3], C1.y, a3);     \
    FMA_F32X2(a0, (W)[ 4], C2.x, a0); FMA_F32X2(a1, (W)[ 5], C2.y, a1);     \
    FMA_F32X2(a2, (W)[ 6], C3.x, a2); FMA_F32X2(a3, (W)[ 7], C3.y, a3);     \
    FMA_F32X2(a0, (W)[ 8], C4.x, a0); FMA_F32X2(a1, (W)[ 9], C4.y, a1);     \
    FMA_F32X2(a2, (W)[10], C5.x, a2); FMA_F32X2(a3, (W)[11], C5.y, a3);     \
    FMA_F32X2(a0, (W)[12], C6.x, a0); FMA_F32X2(a1, (W)[13], C6.y, a1);     \
    FMA_F32X2(a2, (W)[14], C7.x, a2); FMA_F32X2(a3, (W)[15], C7.y, a3);

// One scan step. IG preloaded (pre-bar). Leaves h in HOUT (reg); STG done
// by the caller AFTER the barrier (fire-and-forget in next step's shadow).
#define SCAN_STEP(HSRC, HDST, IG, HOUT)                                      \
{                                                                            \
    const ulonglong2* h2 = (const ulonglong2*)(HSRC);                        \
    ull a0 = 0ULL, a1 = 0ULL, a2 = 0ULL, a3 = 0ULL;                          \
    ulonglong2 p0 = h2[0], p1 = h2[1], p2 = h2[2], p3 = h2[3];               \
    ulonglong2 p4 = h2[4], p5 = h2[5], p6 = h2[6], p7 = h2[7];               \
    ulonglong2 q0 = h2[ 8], q1 = h2[ 9], q2 = h2[10], q3 = h2[11];           \
    ulonglong2 q4 = h2[12], q5 = h2[13], q6 = h2[14], q7 = h2[15];           \
    FMA_CHUNK(p0,p1,p2,p3,p4,p5,p6,p7, w2 + 0)                               \
    p0 = h2[16]; p1 = h2[17]; p2 = h2[18]; p3 = h2[19];                      \
    p4 = h2[20]; p5 = h2[21]; p6 = h2[22]; p7 = h2[23];                      \
    FMA_CHUNK(q0,q1,q2,q3,q4,q5,q6,q7, w2 + 16)                              \
    q0 = h2[24]; q1 = h2[25]; q2 = h2[26]; q3 = h2[27];                      \
    q4 = h2[28]; q5 = h2[29]; q6 = h2[30]; q7 = h2[31];                      \
    FMA_CHUNK(p0,p1,p2,p3,p4,p5,p6,p7, w2 + 32)                              \
    FMA_CHUNK(q0,q1,q2,q3,q4,q5,q6,q7, w2 + 48)                              \
    ADD_F32X2_(a0, a0, a2);                                                  \
    ADD_F32X2_(a1, a1, a3);                                                  \
    ADD_F32X2_(a0, a0, a1);                                                  \
    float2 sp = *reinterpret_cast<float2*>(&a0);                             \
    float pre = (IG) + (sp.x + sp.y);                                        \
    float th;                                                                \
    asm("tanh.approx.f32 %0, %1;" : "=f"(th) : "f"(pre));                    \
    (HOUT) = fmaf(0.5f, th, 0.5f);                                           \
    (HDST)[j] = (HOUT);                                                      \
    BAR_CONS();                                                              \
}

// ======================================================================
// Fused kernel: 128 CTAs (one per batch) x 256 threads.
//   warps 0-3: PRODUCER — tf32 mma.sync (tensor pipe) -> smem ring
//   warps 4-7: CONSUMER — FFMA2 scan (fma pipe), hi-wid priority
// ======================================================================
extern __shared__ float g_smem[];

__global__ void __launch_bounds__(256, 1) fused_rnn_kernel(
    const float* __restrict__ inp,      // [B,T,NI]
    const float* __restrict__ hidden0,  // [B,NH]
    const float* __restrict__ W_in,     // [NH,NI]
    const float* __restrict__ b_in,     // [NH]
    const float* __restrict__ W_hh,     // [NH,NH]
    const float* __restrict__ b_hh,     // [NH]
    float* __restrict__ out)            // [B,T,NH]
{
    float* Whi  = g_smem + WHI_F;
    float* Wlo  = g_smem + WLO_F;
    float* AF   = g_smem + AF_F;
    float* ring = g_smem + RING_F;
    int*  flags = (int*)(g_smem + FLAGS_F);

    const int tid = threadIdx.x;
    const int wid = tid >> 5;
    const int lane = tid & 31;
    const int b = blockIdx.x;

    if (tid == 0) { flags[0] = 0; flags[1] = 0; }

    // ---- W_in hi/lo fragment prep (all 256 threads, once) ----
    for (int idx = tid; idx < 128 * 32; idx += 256) {
        int jj = idx >> 5;
        int g4 = idx & 31;
        int k  = g4 * 4;
        float4 v = *(const float4*)(W_in + (long)jj * NI + k);
        float vf[4] = {v.x, v.y, v.z, v.w};
        int nt = jj >> 3, gg = jj & 7, ks = k >> 3;
        int half = (k & 7) >= 4 ? 1 : 0;
        #pragma unroll
        for (int e = 0; e < 4; e++) {
            uint32_t hu = tf32hi(vf[e]);
            float hf = __uint_as_float(hu);
            uint32_t lu = tf32hi(vf[e] - hf);
            int fa = ((nt * 16 + ks) * 32 + (gg * 4 + e)) * 2 + half;
            Whi[fa] = __uint_as_float(hu);
            Wlo[fa] = __uint_as_float(lu);
        }
    }
    __syncthreads();   // prep done; roles split below

    if (tid < 128) {
        // ============================ PRODUCER ============================
        const float* binp = inp + (long)b * TT * NI;
        const int g  = lane >> 2;   // 0..7
        const int tg = lane & 3;    // 0..3

        float2 biasf[16];
        #pragma unroll
        for (int nt = 0; nt < 16; nt++) {
            int j0 = nt * 8 + tg * 2;
            biasf[nt].x = 0.5f * (b_in[j0]     + b_hh[j0]);
            biasf[nt].y = 0.5f * (b_in[j0 + 1] + b_hh[j0 + 1]);
        }

        for (int kt = 0; kt < N_TILES; kt++) {
            const long t0 = (long)kt * TILE_T;

            if (kt >= 2) {
                while (ld_acquire_shared(&flags[1]) < kt - 1) __nanosleep(64);
            }

            // scatter input tile into A-fragment layout
            #pragma unroll
            for (int it = 0; it < 16; it++) {
                int f = tid + it * 128;          // 0..2047 float4 units
                int r = f >> 5;                  // 0..63
                int g4 = f & 31;
                int k = g4 * 4;
                float4 v = __ldcs((const float4*)(binp + (t0 + r) * NI + k));
                float vf[4] = {v.x, v.y, v.z, v.w};
                int w = r >> 4, ks = k >> 3;
                int reg = (((r & 15) >= 8) ? 1 : 0) + (((k & 7) >= 4) ? 2 : 0);
                int baseaddr = ((w * 16 + ks) * 32 + (r & 7) * 4) * 4 + reg;
                #pragma unroll
                for (int e = 0; e < 4; e++)
                    AF[baseaddr + e * 4] = vf[e];
            }
            BAR_PROD();

            // load this warp's A fragments, split hi/lo
            uint32_t ah[16][4], al[16][4];
            #pragma unroll
            for (int ks = 0; ks < 16; ks++) {
                float4 v = *(const float4*)(AF + ((wid * 16 + ks) * 32 + lane) * 4);
                float vf[4] = {v.x, v.y, v.z, v.w};
                #pragma unroll
                for (int e = 0; e < 4; e++) {
                    ah[ks][e] = tf32hi(vf[e]);
                    al[ks][e] = tf32hi(vf[e] - __uint_as_float(ah[ks][e]));
                }
            }

            // 16 n-tiles x 16 k-steps x 3 mma
            #pragma unroll 1
            for (int nt = 0; nt < 16; nt++) {
                float c0 = 0.f, c1 = 0.f, c2 = 0.f, c3 = 0.f;
                const float2* bhp = (const float2*)(Whi + (nt * 16 * 32) * 2) + lane;
                const float2* blp = (const float2*)(Wlo + (nt * 16 * 32) * 2) + lane;
                #pragma unroll
                for (int ks = 0; ks < 16; ks++) {
                    float2 bh = bhp[ks * 32];
                    float2 bl = blp[ks * 32];
                    uint32_t bh0 = __float_as_uint(bh.x), bh1 = __float_as_uint(bh.y);
                    uint32_t bl0 = __float_as_uint(bl.x), bl1 = __float_as_uint(bl.y);
                    MMA_TF32(c0,c1,c2,c3, ah[ks][0],ah[ks][1],ah[ks][2],ah[ks][3], bh0,bh1);
                    MMA_TF32(c0,c1,c2,c3, al[ks][0],al[ks][1],al[ks][2],al[ks][3], bh0,bh1);
                    MMA_TF32(c0,c1,c2,c3, ah[ks][0],ah[ks][1],ah[ks][2],ah[ks][3], bl0,bl1);
                }
                int j0 = nt * 8 + tg * 2;
                int slot0 = (int)((t0 + wid * 16 + g) & (RING_SLOTS - 1));
                int slot1 = (int)((t0 + wid * 16 + g + 8) & (RING_SLOTS - 1));
                *(float2*)(ring + slot0 * NH + j0) =
                    make_float2(fmaf(0.5f, c0, biasf[nt].x), fmaf(0.5f, c1, biasf[nt].y));
                *(float2*)(ring + slot1 * NH + j0) =
                    make_float2(fmaf(0.5f, c2, biasf[nt].x), fmaf(0.5f, c3, biasf[nt].y));
            }
            BAR_PROD();
            if (tid == 0) st_release_shared(&flags[0], kt + 1);
        }
    } else {
        // ============================ CONSUMER ============================
        const int j = tid - 128;
        float* hA = g_smem + HA_F;
        float* hB = g_smem + HB_F;

        // 0.5*W_hh[j][*] as 64 packed pairs (128 regs)
        ull w2[64];
        {
            const float4* wrow = (const float4*)(W_hh + (long)j * NH);
            #pragma unroll
            for (int i = 0; i < 32; i++) {
                float4 v = wrow[i];
                PACK2_F32X2(w2[2 * i],     0.5f * v.x, 0.5f * v.y);
                PACK2_F32X2(w2[2 * i + 1], 0.5f * v.z, 0.5f * v.w);
            }
        }

        hA[j] = hidden0[(long)b * NH + j];
        float* rowp = out + (long)b * TT * NH + j;

        BAR_CONS();   // hA visible to all consumer threads

        #pragma unroll 1
        for (int tb = 0; tb < N_TILES; tb++) {
            while (ld_acquire_shared(&flags[0]) < tb + 1) __nanosleep(64);
            const float* igp = ring + (long)((tb & 1) * TILE_T) * NH + j;

            #pragma unroll 1
            for (int tt = 0; tt < TILE_T; tt += 2) {
                // both steps' ig preloaded before step A's FMA block
                float iga = igp[0];
                float igb = igp[NH];
                igp += 2 * NH;

                float ha, hbv;
                SCAN_STEP(hA, hB, iga, ha)
                __stcs(rowp, ha); rowp += NH;     // post-bar, in B's shadow
                SCAN_STEP(hB, hA, igb, hbv)
                __stcs(rowp, hbv); rowp += NH;    // post-bar, in next shadow
            }
            if (j == 0) st_release_shared(&flags[1], tb + 1);
        }
    }
}

// ======================================================================
extern "C" void kernel_launch(void* const* d_in, const int* in_sizes, int n_in,
                              void* d_out, int out_size)
{
    const float* inp     = (const float*)d_in[0];  // [B,T,NI]
    const float* hidden0 = (const float*)d_in[1];  // [B,NH]
    const float* W_in    = (const float*)d_in[2];  // [NH,NI]
    const float* b_in    = (const float*)d_in[3];  // [NH]
    const float* W_hh    = (const float*)d_in[4];  // [NH,NH]
    const float* b_hh    = (const float*)d_in[5];  // [NH]
    float* out = (float*)d_out;                    // [B,T,NH]

    const int smem_bytes = SMEM_F * 4;   // 230432 B
    cudaFuncSetAttribute(fused_rnn_kernel,
                         cudaFuncAttributeMaxDynamicSharedMemorySize, smem_bytes);

    fused_rnn_kernel<<<BB, 256, smem_bytes>>>(inp, hidden0, W_in, b_in,
                                              W_hh, b_hh, out);
}